// round 15
// baseline (speedup 1.0000x reference)
#include <cuda_runtime.h>
#include <cstdint>

// Problem constants
#define BB   2
#define SS   2048
#define EE   2048
#define HQ   32
#define HKV  8
#define DD   64
#define KVD  512
// softmax scale folded into Q at projection time: 0.125 * log2(e)
#define QSCALE 0.18033688011112042f

// Scratch (device globals: allocation-free)
__device__ float g_q   [(long long)BB*SS*EE];    // tf32, pre-scaled
__device__ float g_k   [(long long)BB*SS*KVD];   // tf32
__device__ float g_v   [(long long)BB*SS*KVD];   // tf32
__device__ float g_ctx [(long long)BB*SS*EE];    // tf32-rounded (combined)
__device__ float g_oct0[(long long)BB*SS*EE];    // partial O, half 0
__device__ float g_oct1[(long long)BB*SS*EE];    // partial O, half 1
__device__ float g_ps0 [(long long)BB*HQ*SS];    // partial row sums, half 0
__device__ float g_ps1 [(long long)BB*HQ*SS];    // partial row sums, half 1
__device__ float g_rowi[(long long)BB*HQ*SS];    // per-row 1/sum
// pre-rounded (tf32/RNA) copies of inputs + weights
__device__ float g_rq_in[(long long)BB*SS*EE];
__device__ float g_rk_in[(long long)BB*SS*EE];
__device__ float g_rv_in[(long long)BB*SS*EE];
__device__ float g_wq[(long long)EE*EE];
__device__ float g_wk[(long long)EE*KVD];
__device__ float g_wv[(long long)EE*KVD];
__device__ float g_wo[(long long)EE*EE];

// ---------------------------------------------------------------------------
// helpers
// ---------------------------------------------------------------------------
__device__ __forceinline__ uint32_t f2tf32(float x) {
    uint32_t u;
    asm volatile("cvt.rna.tf32.f32 %0, %1;" : "=r"(u) : "f"(x));
    return u;
}
__device__ __forceinline__ float tfb(float x) {
    return __uint_as_float(f2tf32(x));
}
__device__ __forceinline__ float ex2f(float x) {
    float y;
    asm("ex2.approx.ftz.f32 %0, %1;" : "=f"(y) : "f"(x));
    return y;
}

__device__ __forceinline__ void mma_tf32(float c[4], const uint32_t a[4],
                                         const uint32_t b[2]) {
    asm volatile(
        "mma.sync.aligned.m16n8k8.row.col.f32.tf32.tf32.f32 "
        "{%0,%1,%2,%3}, {%4,%5,%6,%7}, {%8,%9}, {%0,%1,%2,%3};\n"
        : "+f"(c[0]), "+f"(c[1]), "+f"(c[2]), "+f"(c[3])
        : "r"(a[0]), "r"(a[1]), "r"(a[2]), "r"(a[3]), "r"(b[0]), "r"(b[1]));
}

__device__ __forceinline__ uint32_t s2u(const void* p) {
    return (uint32_t)__cvta_generic_to_shared(p);
}
__device__ __forceinline__ void cp16(uint32_t s, const float* g) {
    asm volatile("cp.async.cg.shared.global [%0], [%1], 16;" :: "r"(s), "l"(g));
}
#define CPCOMMIT() asm volatile("cp.async.commit_group;")
#define CPWAIT(N)  asm volatile("cp.async.wait_group %0;" :: "n"(N) : "memory")

// ---------------------------------------------------------------------------
// Merged elementwise tf32 (RNA) pre-round of all inputs + weights.
// Compile-time segment bounds; grid-stride float4.
// ---------------------------------------------------------------------------
__global__ void __launch_bounds__(256)
round_all_kernel(const float* __restrict__ q_in, const float* __restrict__ k_in,
                 const float* __restrict__ v_in,
                 const float* __restrict__ wq_in, const float* __restrict__ wk_in,
                 const float* __restrict__ wv_in, const float* __restrict__ wo_in,
                 float* __restrict__ rq, float* __restrict__ rk,
                 float* __restrict__ rv,
                 float* __restrict__ wq, float* __restrict__ wk,
                 float* __restrict__ wv, float* __restrict__ wo)
{
    constexpr int NIN = BB * SS * EE / 4;   // 2,097,152
    constexpr int NWQ = EE * EE / 4;        // 1,048,576
    constexpr int NWK = EE * KVD / 4;       // 262,144
    constexpr int E0 = NIN, E1 = 2 * NIN, E2 = 3 * NIN;
    constexpr int E3 = E2 + NWQ, E4 = E3 + NWK, E5 = E4 + NWK;
    constexpr int TOT = E5 + NWQ;

    for (int i = blockIdx.x * 256 + threadIdx.x; i < TOT; i += gridDim.x * 256) {
        const float4* s;
        float4* d;
        int j;
        if      (i < E0) { s = (const float4*)q_in;  d = (float4*)rq; j = i; }
        else if (i < E1) { s = (const float4*)k_in;  d = (float4*)rk; j = i - E0; }
        else if (i < E2) { s = (const float4*)v_in;  d = (float4*)rv; j = i - E1; }
        else if (i < E3) { s = (const float4*)wq_in; d = (float4*)wq; j = i - E2; }
        else if (i < E4) { s = (const float4*)wk_in; d = (float4*)wk; j = i - E3; }
        else if (i < E5) { s = (const float4*)wv_in; d = (float4*)wv; j = i - E4; }
        else             { s = (const float4*)wo_in; d = (float4*)wo; j = i - E5; }
        float4 t = s[j];
        t.x = tfb(t.x); t.y = tfb(t.y); t.z = tfb(t.z); t.w = tfb(t.w);
        d[j] = t;
    }
}

// ---------------------------------------------------------------------------
// Projection GEMM: C = (A @ W + bias) * oscale [, tf32-rounded if oround].
// A and W must be PRE-ROUNDED tf32 — inner loop has zero cvt.
// ---------------------------------------------------------------------------
#define PR_BYTES (17920 * 4)
__global__ void __launch_bounds__(256, 2)
gemm_nn_bias(const float* __restrict__ A, int lda,
             const float* __restrict__ W, int ldw,
             const float* __restrict__ bias,
             float* __restrict__ C, int ldc, int K,
             float oscale, int oround)
{
    extern __shared__ float sm[];
    float* Asb[2] = { sm,        sm + 4608 };
    float* Bsb[2] = { sm + 9216, sm + 13568 };

    const int brow = blockIdx.y * 128, bcol = blockIdx.x * 128;
    const int tid  = threadIdx.x;
    const int wid  = tid >> 5, lane = tid & 31;
    const int gid  = lane >> 2, tig = lane & 3;
    const int wm   = (wid >> 2) * 64, wn = (wid & 3) * 32;

    float acc[4][4][4];
#pragma unroll
    for (int i = 0; i < 4; i++)
#pragma unroll
        for (int j = 0; j < 4; j++)
#pragma unroll
            for (int r = 0; r < 4; r++) acc[i][j][r] = 0.f;

#define PROJ_LOAD(Ad, Bd, K0) do {                                           \
    _Pragma("unroll")                                                        \
    for (int idx = tid * 4; idx < 128 * 32; idx += 1024) {                   \
        int r = idx >> 5, c = idx & 31;                                      \
        cp16(s2u((Ad) + r * 36 + c),                                         \
             A + (long long)(brow + r) * lda + (K0) + c);                    \
    }                                                                        \
    _Pragma("unroll")                                                        \
    for (int idx = tid * 4; idx < 32 * 128; idx += 1024) {                   \
        int r = idx >> 7, c = idx & 127;                                     \
        cp16(s2u((Bd) + r * 136 + c),                                        \
             W + (long long)((K0) + r) * ldw + bcol + c);                    \
    }                                                                        \
    CPCOMMIT(); } while (0)

    PROJ_LOAD(Asb[0], Bsb[0], 0);
    const int nk = K / 32;
    for (int t = 0; t < nk; t++) {
        const float* Ap = Asb[t & 1];
        const float* Bp = Bsb[t & 1];
        CPWAIT(0);
        __syncthreads();
        if (t + 1 < nk) PROJ_LOAD(Asb[(t + 1) & 1], Bsb[(t + 1) & 1], (t + 1) * 32);

#pragma unroll
        for (int kk = 0; kk < 32; kk += 8) {
            uint32_t af[4][4], bf[4][2];
#pragma unroll
            for (int i = 0; i < 4; i++) {
                int r = wm + 16 * i + gid;
                af[i][0] = __float_as_uint(Ap[r * 36 + kk + tig]);
                af[i][1] = __float_as_uint(Ap[(r + 8) * 36 + kk + tig]);
                af[i][2] = __float_as_uint(Ap[r * 36 + kk + tig + 4]);
                af[i][3] = __float_as_uint(Ap[(r + 8) * 36 + kk + tig + 4]);
            }
#pragma unroll
            for (int j = 0; j < 4; j++) {
                int c = wn + 8 * j + gid;
                bf[j][0] = __float_as_uint(Bp[(kk + tig) * 136 + c]);
                bf[j][1] = __float_as_uint(Bp[(kk + tig + 4) * 136 + c]);
            }
#pragma unroll
            for (int i = 0; i < 4; i++)
#pragma unroll
                for (int j = 0; j < 4; j++)
                    mma_tf32(acc[i][j], af[i], bf[j]);
        }
    }

#pragma unroll
    for (int i = 0; i < 4; i++) {
        int r0 = brow + wm + 16 * i + gid;
#pragma unroll
        for (int j = 0; j < 4; j++) {
            int c0 = bcol + wn + 8 * j + tig * 2;
            float b0 = bias[c0], b1 = bias[c0 + 1];
            float2 o0, o1;
            o0.x = (acc[i][j][0] + b0) * oscale;
            o0.y = (acc[i][j][1] + b1) * oscale;
            o1.x = (acc[i][j][2] + b0) * oscale;
            o1.y = (acc[i][j][3] + b1) * oscale;
            if (oround) {
                o0.x = tfb(o0.x); o0.y = tfb(o0.y);
                o1.x = tfb(o1.x); o1.y = tfb(o1.y);
            }
            *reinterpret_cast<float2*>(C + (long long)r0 * ldc + c0)       = o0;
            *reinterpret_cast<float2*>(C + (long long)(r0 + 8) * ldc + c0) = o1;
        }
    }
#undef PROJ_LOAD
}

// ---------------------------------------------------------------------------
// Pass 1 (split-K): partial row sums of exp2(q'.k) over K-tiles [t0, t1).
// Grid (SS/128, B*HQ, 2), 256 threads. blockIdx.z selects half.
// ---------------------------------------------------------------------------
#define ST_BYTES (17664 * 4)
__global__ void __launch_bounds__(256, 2)
stats_kernel(const float* __restrict__ q, const float* __restrict__ k,
             float* __restrict__ ps0_g, float* __restrict__ ps1_g)
{
    extern __shared__ float sm[];
    float* Qs   = sm;                            // 8704
    float* Ksb[2] = { sm + 8704, sm + 13056 };   // 4352 each
    float* reds = sm + 17408;                    // 256

    const int rb = blockIdx.x, z = blockIdx.y, half = blockIdx.z;
    const int t0 = half * 16, t1 = t0 + 16;
    float* ps_g = half ? ps1_g : ps0_g;

    const int b = z >> 5, h = z & 31, hk = h >> 2;
    const int tid = threadIdx.x, wid = tid >> 5, lane = tid & 31;
    const int gid = lane >> 2, tig = lane & 3;
    const int wmS = (wid >> 1) * 32, wnS = (wid & 1) * 32, wnIdx = wid & 1;

    const float* Qg = q + (long long)b * SS * EE + h * DD + (long long)rb * 128 * EE;
    const float* Kg = k + (long long)b * SS * KVD + hk * DD;

#pragma unroll
    for (int idx = tid * 4; idx < 128 * 64; idx += 1024) {
        int r = idx >> 6, c = idx & 63;
        *reinterpret_cast<float4*>(Qs + r * 68 + c) =
            *reinterpret_cast<const float4*>(Qg + (long long)r * EE + c);
    }

#define K_LOAD(Dst, KT) do {                                                 \
    _Pragma("unroll")                                                        \
    for (int idx = tid * 4; idx < 64 * 64; idx += 1024) {                    \
        int r = idx >> 6, c = idx & 63;                                      \
        cp16(s2u((Dst) + r * 68 + c),                                        \
             Kg + (long long)((KT) + r) * KVD + c);                          \
    }                                                                        \
    CPCOMMIT(); } while (0)

    K_LOAD(Ksb[t0 & 1], t0 * 64);

    float os[2][2];
    os[0][0] = 0.f; os[0][1] = 0.f; os[1][0] = 0.f; os[1][1] = 0.f;

    for (int t = t0; t < t1; t++) {
        const float* Kp = Ksb[t & 1];
        CPWAIT(0);
        __syncthreads();
        if (t + 1 < t1) K_LOAD(Ksb[(t + 1) & 1], (t + 1) * 64);

        float acc[2][4][4];
#pragma unroll
        for (int i = 0; i < 2; i++)
#pragma unroll
            for (int j = 0; j < 4; j++)
#pragma unroll
                for (int r = 0; r < 4; r++) acc[i][j][r] = 0.f;

#pragma unroll
        for (int kk = 0; kk < 64; kk += 8) {
            uint32_t af[2][4], bf[4][2];
#pragma unroll
            for (int i = 0; i < 2; i++) {
                int r = wmS + 16 * i + gid;
                af[i][0] = __float_as_uint(Qs[r * 68 + kk + tig]);
                af[i][1] = __float_as_uint(Qs[(r + 8) * 68 + kk + tig]);
                af[i][2] = __float_as_uint(Qs[r * 68 + kk + tig + 4]);
                af[i][3] = __float_as_uint(Qs[(r + 8) * 68 + kk + tig + 4]);
            }
#pragma unroll
            for (int j = 0; j < 4; j++) {
                int key = wnS + 8 * j + gid;
                bf[j][0] = __float_as_uint(Kp[key * 68 + kk + tig]);
                bf[j][1] = __float_as_uint(Kp[key * 68 + kk + tig + 4]);
            }
#pragma unroll
            for (int i = 0; i < 2; i++)
#pragma unroll
                for (int j = 0; j < 4; j++)
                    mma_tf32(acc[i][j], af[i], bf[j]);
        }

#pragma unroll
        for (int i = 0; i < 2; i++) {
            float s0 = 0.f, s1 = 0.f;
#pragma unroll
            for (int j = 0; j < 4; j++) {
                s0 += ex2f(acc[i][j][0]) + ex2f(acc[i][j][1]);
                s1 += ex2f(acc[i][j][2]) + ex2f(acc[i][j][3]);
            }
            os[i][0] += s0;
            os[i][1] += s1;
        }
    }
#undef K_LOAD

#pragma unroll
    for (int off = 1; off <= 2; off <<= 1)
#pragma unroll
        for (int i = 0; i < 2; i++) {
            os[i][0] += __shfl_xor_sync(~0u, os[i][0], off);
            os[i][1] += __shfl_xor_sync(~0u, os[i][1], off);
        }
    if (tig == 0) {
#pragma unroll
        for (int i = 0; i < 2; i++) {
            reds[wnIdx * 128 + wmS + 16 * i + gid]     = os[i][0];
            reds[wnIdx * 128 + wmS + 16 * i + gid + 8] = os[i][1];
        }
    }
    __syncthreads();
    if (tid < 128) {
        long long row = (long long)z * SS + rb * 128 + tid;
        ps_g[row] = reds[tid] + reds[128 + tid];
    }
}

// rowi = 1 / (ps0 + ps1)
__global__ void __launch_bounds__(256)
inv_kernel(const float* __restrict__ p0, const float* __restrict__ p1,
           float* __restrict__ rowi, int n)
{
    int i = blockIdx.x * 256 + threadIdx.x;
    if (i < n) rowi[i] = 1.0f / (p0[i] + p1[i]);
}

// ---------------------------------------------------------------------------
// Pass 2 (split-K): K-tiles [t0, t1). Writes its attn column range (disjoint)
// and a partial O (raw fp32) to its half's scratch buffer.
// Grid (SS/128, B*HQ, 2), 256 threads.
// ---------------------------------------------------------------------------
#define P2_BYTES (26496 * 4)
__global__ void __launch_bounds__(256, 2)
attnpv_kernel(const float* __restrict__ q, const float* __restrict__ k,
              const float* __restrict__ v, const float* __restrict__ rowi_g,
              float* __restrict__ attn,
              float* __restrict__ oct0, float* __restrict__ oct1)
{
    extern __shared__ float sm[];
    float* Qs = sm;            // 8704
    float* Ks = sm + 8704;     // 4352  (64 keys x 68)
    float* Vs = sm + 13056;    // 4608  (64 keys x 72)
    float* Ps = sm + 17664;    // 8704  (128 x 68)
    float* ri = sm + 26368;    // 128

    const int rb = blockIdx.x, z = blockIdx.y, half = blockIdx.z;
    const int t0 = half * 16, t1 = t0 + 16;
    float* octx = half ? oct1 : oct0;

    const int b = z >> 5, h = z & 31, hk = h >> 2;
    const int tid = threadIdx.x, wid = tid >> 5, lane = tid & 31;
    const int gid = lane >> 2, tig = lane & 3;
    const int wmS = (wid >> 1) * 32, wnS = (wid & 1) * 32;

    const float* Qg = q + (long long)b * SS * EE + h * DD + (long long)rb * 128 * EE;
    const float* Kg = k + (long long)b * SS * KVD + hk * DD;
    const float* Vg = v + (long long)b * SS * KVD + hk * DD;
    float*       Ag = attn + (long long)z * SS * SS + (long long)rb * 128 * SS;

#pragma unroll
    for (int idx = tid * 4; idx < 128 * 64; idx += 1024) {
        int r = idx >> 6, c = idx & 63;
        *reinterpret_cast<float4*>(Qs + r * 68 + c) =
            *reinterpret_cast<const float4*>(Qg + (long long)r * EE + c);
    }
    if (tid < 128) {
        long long row = (long long)z * SS + rb * 128 + tid;
        ri[tid] = rowi_g[row];
    }

#define K_LOAD2(KT) do {                                                     \
    _Pragma("unroll")                                                        \
    for (int idx = tid * 4; idx < 64 * 64; idx += 1024) {                    \
        int r = idx >> 6, c = idx & 63;                                      \
        cp16(s2u(Ks + r * 68 + c), Kg + (long long)((KT) + r) * KVD + c);    \
    }                                                                        \
    CPCOMMIT(); } while (0)
#define V_LOAD2(KT) do {                                                     \
    _Pragma("unroll")                                                        \
    for (int idx = tid * 4; idx < 64 * 64; idx += 1024) {                    \
        int r = idx >> 6, c = idx & 63;                                      \
        cp16(s2u(Vs + r * 72 + c), Vg + (long long)((KT) + r) * KVD + c);    \
    }                                                                        \
    CPCOMMIT(); } while (0)

    K_LOAD2(t0 * 64);   // pending: {K_t0}

    float oacc[2][4][4];
#pragma unroll
    for (int i = 0; i < 2; i++)
#pragma unroll
        for (int j = 0; j < 4; j++)
#pragma unroll
            for (int r = 0; r < 4; r++) oacc[i][j][r] = 0.f;

    for (int t = t0; t < t1; t++) {
        const int kt = t * 64;
        V_LOAD2(kt);            // pending: {K_t, V_t}
        CPWAIT(1);              // K_t done
        __syncthreads();

        // S = Q @ K^T for this 64-col tile (values are log2-scaled scores)
        float acc[2][4][4];
#pragma unroll
        for (int i = 0; i < 2; i++)
#pragma unroll
            for (int j = 0; j < 4; j++)
#pragma unroll
                for (int r = 0; r < 4; r++) acc[i][j][r] = 0.f;

#pragma unroll
        for (int kk = 0; kk < 64; kk += 8) {
            uint32_t af[2][4], bf[4][2];
#pragma unroll
            for (int i = 0; i < 2; i++) {
                int r = wmS + 16 * i + gid;
                af[i][0] = __float_as_uint(Qs[r * 68 + kk + tig]);
                af[i][1] = __float_as_uint(Qs[(r + 8) * 68 + kk + tig]);
                af[i][2] = __float_as_uint(Qs[r * 68 + kk + tig + 4]);
                af[i][3] = __float_as_uint(Qs[(r + 8) * 68 + kk + tig + 4]);
            }
#pragma unroll
            for (int j = 0; j < 4; j++) {
                int key = wnS + 8 * j + gid;
                bf[j][0] = __float_as_uint(Ks[key * 68 + kk + tig]);
                bf[j][1] = __float_as_uint(Ks[key * 68 + kk + tig + 4]);
            }
#pragma unroll
            for (int i = 0; i < 2; i++)
#pragma unroll
                for (int j = 0; j < 4; j++)
                    mma_tf32(acc[i][j], af[i], bf[j]);
        }
        __syncthreads();        // everyone done reading Ks
        if (t + 1 < t1) K_LOAD2(kt + 64);   // pending: {V_t, K_{t+1}}

        // p = exp2(s) * inv; stage raw fp32 P into Ps
#pragma unroll
        for (int i = 0; i < 2; i++) {
            int r0 = wmS + 16 * i + gid;
            float iv0 = ri[r0], iv1 = ri[r0 + 8];
#pragma unroll
            for (int j = 0; j < 4; j++) {
                int c0 = wnS + 8 * j + 2 * tig;
                float2 w0, w1;
                w0.x = ex2f(acc[i][j][0]) * iv0;
                w0.y = ex2f(acc[i][j][1]) * iv0;
                w1.x = ex2f(acc[i][j][2]) * iv1;
                w1.y = ex2f(acc[i][j][3]) * iv1;
                *reinterpret_cast<float2*>(Ps + r0 * 68 + c0)       = w0;
                *reinterpret_cast<float2*>(Ps + (r0 + 8) * 68 + c0) = w1;
            }
        }
        if (t + 1 < t1) { CPWAIT(1); }   // V_t done (K_{t+1} still flying)
        else            { CPWAIT(0); }   // last tile of this half
        __syncthreads();                 // Ps staged + Vs visible

        // attn write: coalesced float4 rows straight from Ps
#pragma unroll
        for (int idx = tid * 4; idx < 128 * 64; idx += 1024) {
            int r = idx >> 6, c = idx & 63;
            *reinterpret_cast<float4*>(Ag + (long long)r * SS + kt + c) =
                *reinterpret_cast<const float4*>(Ps + r * 68 + c);
        }

        // O += P @ V  (k = 64); P bits fed raw (HW tf32 truncation)
#pragma unroll
        for (int kk = 0; kk < 64; kk += 8) {
            uint32_t af[2][4], bf[4][2];
#pragma unroll
            for (int i = 0; i < 2; i++) {
                int r = wmS + 16 * i + gid;
                af[i][0] = __float_as_uint(Ps[r * 68 + kk + tig]);
                af[i][1] = __float_as_uint(Ps[(r + 8) * 68 + kk + tig]);
                af[i][2] = __float_as_uint(Ps[r * 68 + kk + tig + 4]);
                af[i][3] = __float_as_uint(Ps[(r + 8) * 68 + kk + tig + 4]);
            }
#pragma unroll
            for (int j = 0; j < 4; j++) {
                int c = wnS + 8 * j + gid;
                bf[j][0] = __float_as_uint(Vs[(kk + tig) * 72 + c]);
                bf[j][1] = __float_as_uint(Vs[(kk + tig + 4) * 72 + c]);
            }
#pragma unroll
            for (int i = 0; i < 2; i++)
#pragma unroll
                for (int j = 0; j < 4; j++)
                    mma_tf32(oacc[i][j], af[i], bf[j]);
        }
        __syncthreads();             // Ps / Vs free for next iteration
    }
#undef K_LOAD2
#undef V_LOAD2

    // partial-O epilogue (raw fp32): (B,S,32,64)
    float* Cg = octx + (long long)b * SS * EE + (long long)rb * 128 * EE + h * DD;
#pragma unroll
    for (int i = 0; i < 2; i++) {
        int r0 = wmS + 16 * i + gid;
#pragma unroll
        for (int j = 0; j < 4; j++) {
            int c0 = wnS + 8 * j + 2 * tig;
            float2 o0, o1;
            o0.x = oacc[i][j][0]; o0.y = oacc[i][j][1];
            o1.x = oacc[i][j][2]; o1.y = oacc[i][j][3];
            *reinterpret_cast<float2*>(Cg + (long long)r0 * EE + c0)       = o0;
            *reinterpret_cast<float2*>(Cg + (long long)(r0 + 8) * EE + c0) = o1;
        }
    }
}

// ctx = tf32_round(oct0 + oct1)
__global__ void __launch_bounds__(256)
ctx_combine_kernel(const float* __restrict__ a, const float* __restrict__ b,
                   float* __restrict__ ctx, int n4)
{
    int i = blockIdx.x * 256 + threadIdx.x;
    if (i < n4) {
        float4 x = reinterpret_cast<const float4*>(a)[i];
        float4 y = reinterpret_cast<const float4*>(b)[i];
        float4 o;
        o.x = tfb(x.x + y.x); o.y = tfb(x.y + y.y);
        o.z = tfb(x.z + y.z); o.w = tfb(x.w + y.w);
        reinterpret_cast<float4*>(ctx)[i] = o;
    }
}

// ---------------------------------------------------------------------------
// Launch: out (B,S,E) fp32 first, then attn_weights (B,32,S,S) fp32.
// ---------------------------------------------------------------------------
extern "C" void kernel_launch(void* const* d_in, const int* in_sizes, int n_in,
                              void* d_out, int out_size)
{
    const float* query = (const float*)d_in[0];
    const float* key_  = (const float*)d_in[1];
    const float* value = (const float*)d_in[2];
    const float* Wq = (const float*)d_in[3];  const float* bq = (const float*)d_in[4];
    const float* Wk = (const float*)d_in[5];  const float* bk = (const float*)d_in[6];
    const float* Wv = (const float*)d_in[7];  const float* bv = (const float*)d_in[8];
    const float* Wo = (const float*)d_in[9];  const float* bo = (const float*)d_in[10];

    float* out  = (float*)d_out;
    float* attn = out + (long long)BB * SS * EE;

    float *qbuf, *kbuf, *vbuf, *ctx, *oct0, *oct1, *ps0, *ps1, *rowi;
    float *rqi, *rki, *rvi, *wq, *wk, *wv, *wo;
    cudaGetSymbolAddress((void**)&qbuf, g_q);
    cudaGetSymbolAddress((void**)&kbuf, g_k);
    cudaGetSymbolAddress((void**)&vbuf, g_v);
    cudaGetSymbolAddress((void**)&ctx,  g_ctx);
    cudaGetSymbolAddress((void**)&oct0, g_oct0);
    cudaGetSymbolAddress((void**)&oct1, g_oct1);
    cudaGetSymbolAddress((void**)&ps0,  g_ps0);
    cudaGetSymbolAddress((void**)&ps1,  g_ps1);
    cudaGetSymbolAddress((void**)&rowi, g_rowi);
    cudaGetSymbolAddress((void**)&rqi,  g_rq_in);
    cudaGetSymbolAddress((void**)&rki,  g_rk_in);
    cudaGetSymbolAddress((void**)&rvi,  g_rv_in);
    cudaGetSymbolAddress((void**)&wq,   g_wq);
    cudaGetSymbolAddress((void**)&wk,   g_wk);
    cudaGetSymbolAddress((void**)&wv,   g_wv);
    cudaGetSymbolAddress((void**)&wo,   g_wo);

    static bool attr_set = false;
    if (!attr_set) {
        cudaFuncSetAttribute(gemm_nn_bias,
            cudaFuncAttributeMaxDynamicSharedMemorySize, PR_BYTES);
        cudaFuncSetAttribute(stats_kernel,
            cudaFuncAttributeMaxDynamicSharedMemorySize, ST_BYTES);
        cudaFuncSetAttribute(attnpv_kernel,
            cudaFuncAttributeMaxDynamicSharedMemorySize, P2_BYTES);
        attr_set = true;
    }

    const int M = BB * SS;   // 4096
    dim3 blk(256);

    // Pre-round inputs + weights to tf32 (RNA) — one merged launch.
    round_all_kernel<<<4096, blk>>>(query, key_, value, Wq, Wk, Wv, Wo,
                                    rqi, rki, rvi, wq, wk, wv, wo);

    // Projections (cvt-free): q pre-scaled+rounded; k/v rounded.
    gemm_nn_bias<<<dim3(EE/128,  M/128), blk, PR_BYTES>>>(rqi, EE, wq, EE,  bq, qbuf, EE,  EE, QSCALE, 1);
    gemm_nn_bias<<<dim3(KVD/128, M/128), blk, PR_BYTES>>>(rki, EE, wk, KVD, bk, kbuf, KVD, EE, 1.0f,  1);
    gemm_nn_bias<<<dim3(KVD/128, M/128), blk, PR_BYTES>>>(rvi, EE, wv, KVD, bv, vbuf, KVD, EE, 1.0f,  1);

    // Pass 1: split-K partial row sums of exp2, then combine to 1/sum.
    stats_kernel<<<dim3(SS/128, BB*HQ, 2), blk, ST_BYTES>>>(qbuf, kbuf, ps0, ps1);
    inv_kernel<<<(BB*HQ*SS)/256, blk>>>(ps0, ps1, rowi, BB*HQ*SS);

    // Pass 2: split-K recompute + normalize + attn write + partial P@V.
    attnpv_kernel<<<dim3(SS/128, BB*HQ, 2), blk, P2_BYTES>>>(
        qbuf, kbuf, vbuf, rowi, attn, oct0, oct1);

    // Combine partial O halves (tf32-rounded for cvt-free output proj).
    ctx_combine_kernel<<<(BB*SS*EE/4 + 255)/256, blk>>>(oct0, oct1, ctx, BB*SS*EE/4);

    // Output projection (fp32 out, no out-rounding).
    gemm_nn_bias<<<dim3(EE/128, M/128), blk, PR_BYTES>>>(ctx, EE, wo, EE, bo, out, EE, EE, 1.0f, 0);
}

// round 16
// speedup vs baseline: 1.0181x; 1.0181x over previous
#include <cuda_runtime.h>
#include <cstdint>

// Problem constants
#define BB   2
#define SS   2048
#define EE   2048
#define HQ   32
#define HKV  8
#define DD   64
#define KVD  512
// softmax scale folded into Q at projection time: 0.125 * log2(e)
#define QSCALE 0.18033688011112042f

// Scratch (device globals: allocation-free)
__device__ float g_q   [(long long)BB*SS*EE];    // tf32, pre-scaled
__device__ float g_k   [(long long)BB*SS*KVD];   // tf32
__device__ float g_v   [(long long)BB*SS*KVD];   // tf32
__device__ float g_ctx [(long long)BB*SS*EE];    // tf32-rounded (combined)
__device__ float g_oct0[(long long)BB*SS*EE];    // partial O, half 0
__device__ float g_oct1[(long long)BB*SS*EE];    // partial O, half 1
__device__ float g_ps0 [(long long)BB*HQ*SS];    // partial row sums, half 0
__device__ float g_ps1 [(long long)BB*HQ*SS];    // partial row sums, half 1
__device__ float g_rowi[(long long)BB*HQ*SS];    // per-row 1/sum
// pre-rounded (tf32/RNA) copies of inputs + weights
__device__ float g_rq_in[(long long)BB*SS*EE];
__device__ float g_rk_in[(long long)BB*SS*EE];
__device__ float g_rv_in[(long long)BB*SS*EE];
__device__ float g_wq[(long long)EE*EE];
__device__ float g_wk[(long long)EE*KVD];
__device__ float g_wv[(long long)EE*KVD];
__device__ float g_wo[(long long)EE*EE];

// ---------------------------------------------------------------------------
// helpers
// ---------------------------------------------------------------------------
__device__ __forceinline__ uint32_t f2tf32(float x) {
    uint32_t u;
    asm volatile("cvt.rna.tf32.f32 %0, %1;" : "=r"(u) : "f"(x));
    return u;
}
__device__ __forceinline__ float tfb(float x) {
    return __uint_as_float(f2tf32(x));
}
__device__ __forceinline__ float ex2f(float x) {
    float y;
    asm("ex2.approx.ftz.f32 %0, %1;" : "=f"(y) : "f"(x));
    return y;
}

__device__ __forceinline__ void mma_tf32(float c[4], const uint32_t a[4],
                                         const uint32_t b[2]) {
    asm volatile(
        "mma.sync.aligned.m16n8k8.row.col.f32.tf32.tf32.f32 "
        "{%0,%1,%2,%3}, {%4,%5,%6,%7}, {%8,%9}, {%0,%1,%2,%3};\n"
        : "+f"(c[0]), "+f"(c[1]), "+f"(c[2]), "+f"(c[3])
        : "r"(a[0]), "r"(a[1]), "r"(a[2]), "r"(a[3]), "r"(b[0]), "r"(b[1]));
}

__device__ __forceinline__ uint32_t s2u(const void* p) {
    return (uint32_t)__cvta_generic_to_shared(p);
}
__device__ __forceinline__ void cp16(uint32_t s, const float* g) {
    asm volatile("cp.async.cg.shared.global [%0], [%1], 16;" :: "r"(s), "l"(g));
}
#define CPCOMMIT() asm volatile("cp.async.commit_group;")
#define CPWAIT(N)  asm volatile("cp.async.wait_group %0;" :: "n"(N) : "memory")

// ---------------------------------------------------------------------------
// Merged elementwise tf32 (RNA) pre-round of all inputs + weights.
// ---------------------------------------------------------------------------
__global__ void __launch_bounds__(256)
round_all_kernel(const float* __restrict__ q_in, const float* __restrict__ k_in,
                 const float* __restrict__ v_in,
                 const float* __restrict__ wq_in, const float* __restrict__ wk_in,
                 const float* __restrict__ wv_in, const float* __restrict__ wo_in,
                 float* __restrict__ rq, float* __restrict__ rk,
                 float* __restrict__ rv,
                 float* __restrict__ wq, float* __restrict__ wk,
                 float* __restrict__ wv, float* __restrict__ wo)
{
    constexpr int NIN = BB * SS * EE / 4;   // 2,097,152
    constexpr int NWQ = EE * EE / 4;        // 1,048,576
    constexpr int NWK = EE * KVD / 4;       // 262,144
    constexpr int E0 = NIN, E1 = 2 * NIN, E2 = 3 * NIN;
    constexpr int E3 = E2 + NWQ, E4 = E3 + NWK, E5 = E4 + NWK;
    constexpr int TOT = E5 + NWQ;

    for (int i = blockIdx.x * 256 + threadIdx.x; i < TOT; i += gridDim.x * 256) {
        const float4* s;
        float4* d;
        int j;
        if      (i < E0) { s = (const float4*)q_in;  d = (float4*)rq; j = i; }
        else if (i < E1) { s = (const float4*)k_in;  d = (float4*)rk; j = i - E0; }
        else if (i < E2) { s = (const float4*)v_in;  d = (float4*)rv; j = i - E1; }
        else if (i < E3) { s = (const float4*)wq_in; d = (float4*)wq; j = i - E2; }
        else if (i < E4) { s = (const float4*)wk_in; d = (float4*)wk; j = i - E3; }
        else if (i < E5) { s = (const float4*)wv_in; d = (float4*)wv; j = i - E4; }
        else             { s = (const float4*)wo_in; d = (float4*)wo; j = i - E5; }
        float4 t = s[j];
        t.x = tfb(t.x); t.y = tfb(t.y); t.z = tfb(t.z); t.w = tfb(t.w);
        d[j] = t;
    }
}

// ---------------------------------------------------------------------------
// Shared GEMM core (pre-rounded operands, cvt-free inner loop).
// C = (A @ W + bias) * oscale [, tf32-rounded if oround]. K fixed = EE.
// ---------------------------------------------------------------------------
#define PR_BYTES (17920 * 4)
__device__ __forceinline__ void proj_core(
    const float* __restrict__ A, const float* __restrict__ W, int ldw,
    const float* __restrict__ bias, float* __restrict__ C, int ldc,
    float oscale, int oround, int brow, int bcol)
{
    extern __shared__ float sm[];
    float* Asb[2] = { sm,        sm + 4608 };
    float* Bsb[2] = { sm + 9216, sm + 13568 };

    const int tid  = threadIdx.x;
    const int wid  = tid >> 5, lane = tid & 31;
    const int gid  = lane >> 2, tig = lane & 3;
    const int wm   = (wid >> 2) * 64, wn = (wid & 3) * 32;

    float acc[4][4][4];
#pragma unroll
    for (int i = 0; i < 4; i++)
#pragma unroll
        for (int j = 0; j < 4; j++)
#pragma unroll
            for (int r = 0; r < 4; r++) acc[i][j][r] = 0.f;

#define PROJ_LOAD(Ad, Bd, K0) do {                                           \
    _Pragma("unroll")                                                        \
    for (int idx = tid * 4; idx < 128 * 32; idx += 1024) {                   \
        int r = idx >> 5, c = idx & 31;                                      \
        cp16(s2u((Ad) + r * 36 + c),                                         \
             A + (long long)(brow + r) * EE + (K0) + c);                     \
    }                                                                        \
    _Pragma("unroll")                                                        \
    for (int idx = tid * 4; idx < 32 * 128; idx += 1024) {                   \
        int r = idx >> 7, c = idx & 127;                                     \
        cp16(s2u((Bd) + r * 136 + c),                                        \
             W + (long long)((K0) + r) * ldw + bcol + c);                    \
    }                                                                        \
    CPCOMMIT(); } while (0)

    PROJ_LOAD(Asb[0], Bsb[0], 0);
    const int nk = EE / 32;
    for (int t = 0; t < nk; t++) {
        const float* Ap = Asb[t & 1];
        const float* Bp = Bsb[t & 1];
        CPWAIT(0);
        __syncthreads();
        if (t + 1 < nk) PROJ_LOAD(Asb[(t + 1) & 1], Bsb[(t + 1) & 1], (t + 1) * 32);

#pragma unroll
        for (int kk = 0; kk < 32; kk += 8) {
            uint32_t af[4][4], bf[4][2];
#pragma unroll
            for (int i = 0; i < 4; i++) {
                int r = wm + 16 * i + gid;
                af[i][0] = __float_as_uint(Ap[r * 36 + kk + tig]);
                af[i][1] = __float_as_uint(Ap[(r + 8) * 36 + kk + tig]);
                af[i][2] = __float_as_uint(Ap[r * 36 + kk + tig + 4]);
                af[i][3] = __float_as_uint(Ap[(r + 8) * 36 + kk + tig + 4]);
            }
#pragma unroll
            for (int j = 0; j < 4; j++) {
                int c = wn + 8 * j + gid;
                bf[j][0] = __float_as_uint(Bp[(kk + tig) * 136 + c]);
                bf[j][1] = __float_as_uint(Bp[(kk + tig + 4) * 136 + c]);
            }
#pragma unroll
            for (int i = 0; i < 4; i++)
#pragma unroll
                for (int j = 0; j < 4; j++)
                    mma_tf32(acc[i][j], af[i], bf[j]);
        }
    }

#pragma unroll
    for (int i = 0; i < 4; i++) {
        int r0 = brow + wm + 16 * i + gid;
#pragma unroll
        for (int j = 0; j < 4; j++) {
            int c0 = bcol + wn + 8 * j + tig * 2;
            float b0 = bias[c0], b1 = bias[c0 + 1];
            float2 o0, o1;
            o0.x = (acc[i][j][0] + b0) * oscale;
            o0.y = (acc[i][j][1] + b1) * oscale;
            o1.x = (acc[i][j][2] + b0) * oscale;
            o1.y = (acc[i][j][3] + b1) * oscale;
            if (oround) {
                o0.x = tfb(o0.x); o0.y = tfb(o0.y);
                o1.x = tfb(o1.x); o1.y = tfb(o1.y);
            }
            *reinterpret_cast<float2*>(C + (long long)r0 * ldc + c0)       = o0;
            *reinterpret_cast<float2*>(C + (long long)(r0 + 8) * ldc + c0) = o1;
        }
    }
#undef PROJ_LOAD
}

// ---------------------------------------------------------------------------
// Merged Q/K/V projection: 1-D grid of 768 tiles (Q 512, K 128, V 128).
// All CTAs run the identical K=2048 pipeline — no divergence, full machine.
// ---------------------------------------------------------------------------
__global__ void __launch_bounds__(256, 2)
qkv_proj_kernel(const float* __restrict__ rq, const float* __restrict__ rk,
                const float* __restrict__ rv,
                const float* __restrict__ wq, const float* __restrict__ wk,
                const float* __restrict__ wv,
                const float* __restrict__ bq, const float* __restrict__ bk,
                const float* __restrict__ bv,
                float* __restrict__ qout, float* __restrict__ kout,
                float* __restrict__ vout)
{
    const int tile = blockIdx.x;
    const float *A, *W, *bias;
    float* C;
    int ldw, ldc, brow, bcol;
    float oscale;
    if (tile < 512) {            // Q: 32 row-tiles x 16 col-tiles
        A = rq; W = wq; bias = bq; C = qout; ldw = EE; ldc = EE;
        brow = (tile >> 4) * 128; bcol = (tile & 15) * 128; oscale = QSCALE;
    } else if (tile < 640) {     // K: 32 x 4
        int t = tile - 512;
        A = rk; W = wk; bias = bk; C = kout; ldw = KVD; ldc = KVD;
        brow = (t >> 2) * 128; bcol = (t & 3) * 128; oscale = 1.0f;
    } else {                     // V: 32 x 4
        int t = tile - 640;
        A = rv; W = wv; bias = bv; C = vout; ldw = KVD; ldc = KVD;
        brow = (t >> 2) * 128; bcol = (t & 3) * 128; oscale = 1.0f;
    }
    proj_core(A, W, ldw, bias, C, ldc, oscale, 1, brow, bcol);
}

// Output projection (separate: fp32 out, no rounding).
__global__ void __launch_bounds__(256, 2)
oproj_kernel(const float* __restrict__ ctx, const float* __restrict__ wo,
             const float* __restrict__ bo, float* __restrict__ out)
{
    proj_core(ctx, wo, EE, bo, out, EE, 1.0f, 0,
              blockIdx.y * 128, blockIdx.x * 128);
}

// ---------------------------------------------------------------------------
// Pass 1 (split-K): partial row sums of exp2(q'.k) over K-tiles [t0, t1).
// Grid (SS/128, B*HQ, 2), 256 threads.
// ---------------------------------------------------------------------------
#define ST_BYTES (17664 * 4)
__global__ void __launch_bounds__(256, 2)
stats_kernel(const float* __restrict__ q, const float* __restrict__ k,
             float* __restrict__ ps0_g, float* __restrict__ ps1_g)
{
    extern __shared__ float sm[];
    float* Qs   = sm;                            // 8704
    float* Ksb[2] = { sm + 8704, sm + 13056 };   // 4352 each
    float* reds = sm + 17408;                    // 256

    const int rb = blockIdx.x, z = blockIdx.y, half = blockIdx.z;
    const int t0 = half * 16, t1 = t0 + 16;
    float* ps_g = half ? ps1_g : ps0_g;

    const int b = z >> 5, h = z & 31, hk = h >> 2;
    const int tid = threadIdx.x, wid = tid >> 5, lane = tid & 31;
    const int gid = lane >> 2, tig = lane & 3;
    const int wmS = (wid >> 1) * 32, wnS = (wid & 1) * 32, wnIdx = wid & 1;

    const float* Qg = q + (long long)b * SS * EE + h * DD + (long long)rb * 128 * EE;
    const float* Kg = k + (long long)b * SS * KVD + hk * DD;

#pragma unroll
    for (int idx = tid * 4; idx < 128 * 64; idx += 1024) {
        int r = idx >> 6, c = idx & 63;
        *reinterpret_cast<float4*>(Qs + r * 68 + c) =
            *reinterpret_cast<const float4*>(Qg + (long long)r * EE + c);
    }

#define K_LOAD(Dst, KT) do {                                                 \
    _Pragma("unroll")                                                        \
    for (int idx = tid * 4; idx < 64 * 64; idx += 1024) {                    \
        int r = idx >> 6, c = idx & 63;                                      \
        cp16(s2u((Dst) + r * 68 + c),                                        \
             Kg + (long long)((KT) + r) * KVD + c);                          \
    }                                                                        \
    CPCOMMIT(); } while (0)

    K_LOAD(Ksb[t0 & 1], t0 * 64);

    float os[2][2];
    os[0][0] = 0.f; os[0][1] = 0.f; os[1][0] = 0.f; os[1][1] = 0.f;

    for (int t = t0; t < t1; t++) {
        const float* Kp = Ksb[t & 1];
        CPWAIT(0);
        __syncthreads();
        if (t + 1 < t1) K_LOAD(Ksb[(t + 1) & 1], (t + 1) * 64);

        float acc[2][4][4];
#pragma unroll
        for (int i = 0; i < 2; i++)
#pragma unroll
            for (int j = 0; j < 4; j++)
#pragma unroll
                for (int r = 0; r < 4; r++) acc[i][j][r] = 0.f;

#pragma unroll
        for (int kk = 0; kk < 64; kk += 8) {
            uint32_t af[2][4], bf[4][2];
#pragma unroll
            for (int i = 0; i < 2; i++) {
                int r = wmS + 16 * i + gid;
                af[i][0] = __float_as_uint(Qs[r * 68 + kk + tig]);
                af[i][1] = __float_as_uint(Qs[(r + 8) * 68 + kk + tig]);
                af[i][2] = __float_as_uint(Qs[r * 68 + kk + tig + 4]);
                af[i][3] = __float_as_uint(Qs[(r + 8) * 68 + kk + tig + 4]);
            }
#pragma unroll
            for (int j = 0; j < 4; j++) {
                int key = wnS + 8 * j + gid;
                bf[j][0] = __float_as_uint(Kp[key * 68 + kk + tig]);
                bf[j][1] = __float_as_uint(Kp[key * 68 + kk + tig + 4]);
            }
#pragma unroll
            for (int i = 0; i < 2; i++)
#pragma unroll
                for (int j = 0; j < 4; j++)
                    mma_tf32(acc[i][j], af[i], bf[j]);
        }

#pragma unroll
        for (int i = 0; i < 2; i++) {
            float s0 = 0.f, s1 = 0.f;
#pragma unroll
            for (int j = 0; j < 4; j++) {
                s0 += ex2f(acc[i][j][0]) + ex2f(acc[i][j][1]);
                s1 += ex2f(acc[i][j][2]) + ex2f(acc[i][j][3]);
            }
            os[i][0] += s0;
            os[i][1] += s1;
        }
    }
#undef K_LOAD

#pragma unroll
    for (int off = 1; off <= 2; off <<= 1)
#pragma unroll
        for (int i = 0; i < 2; i++) {
            os[i][0] += __shfl_xor_sync(~0u, os[i][0], off);
            os[i][1] += __shfl_xor_sync(~0u, os[i][1], off);
        }
    if (tig == 0) {
#pragma unroll
        for (int i = 0; i < 2; i++) {
            reds[wnIdx * 128 + wmS + 16 * i + gid]     = os[i][0];
            reds[wnIdx * 128 + wmS + 16 * i + gid + 8] = os[i][1];
        }
    }
    __syncthreads();
    if (tid < 128) {
        long long row = (long long)z * SS + rb * 128 + tid;
        ps_g[row] = reds[tid] + reds[128 + tid];
    }
}

// rowi = 1 / (ps0 + ps1)
__global__ void __launch_bounds__(256)
inv_kernel(const float* __restrict__ p0, const float* __restrict__ p1,
           float* __restrict__ rowi, int n)
{
    int i = blockIdx.x * 256 + threadIdx.x;
    if (i < n) rowi[i] = 1.0f / (p0[i] + p1[i]);
}

// ---------------------------------------------------------------------------
// Pass 2 (split-K): K-tiles [t0, t1). Writes its attn column range (disjoint)
// and a partial O (raw fp32) to its half's scratch buffer.
// Grid (SS/128, B*HQ, 2), 256 threads.
// ---------------------------------------------------------------------------
#define P2_BYTES (26496 * 4)
__global__ void __launch_bounds__(256, 2)
attnpv_kernel(const float* __restrict__ q, const float* __restrict__ k,
              const float* __restrict__ v, const float* __restrict__ rowi_g,
              float* __restrict__ attn,
              float* __restrict__ oct0, float* __restrict__ oct1)
{
    extern __shared__ float sm[];
    float* Qs = sm;            // 8704
    float* Ks = sm + 8704;     // 4352
    float* Vs = sm + 13056;    // 4608
    float* Ps = sm + 17664;    // 8704
    float* ri = sm + 26368;    // 128

    const int rb = blockIdx.x, z = blockIdx.y, half = blockIdx.z;
    const int t0 = half * 16, t1 = t0 + 16;
    float* octx = half ? oct1 : oct0;

    const int b = z >> 5, h = z & 31, hk = h >> 2;
    const int tid = threadIdx.x, wid = tid >> 5, lane = tid & 31;
    const int gid = lane >> 2, tig = lane & 3;
    const int wmS = (wid >> 1) * 32, wnS = (wid & 1) * 32;

    const float* Qg = q + (long long)b * SS * EE + h * DD + (long long)rb * 128 * EE;
    const float* Kg = k + (long long)b * SS * KVD + hk * DD;
    const float* Vg = v + (long long)b * SS * KVD + hk * DD;
    float*       Ag = attn + (long long)z * SS * SS + (long long)rb * 128 * SS;

#pragma unroll
    for (int idx = tid * 4; idx < 128 * 64; idx += 1024) {
        int r = idx >> 6, c = idx & 63;
        *reinterpret_cast<float4*>(Qs + r * 68 + c) =
            *reinterpret_cast<const float4*>(Qg + (long long)r * EE + c);
    }
    if (tid < 128) {
        long long row = (long long)z * SS + rb * 128 + tid;
        ri[tid] = rowi_g[row];
    }

#define K_LOAD2(KT) do {                                                     \
    _Pragma("unroll")                                                        \
    for (int idx = tid * 4; idx < 64 * 64; idx += 1024) {                    \
        int r = idx >> 6, c = idx & 63;                                      \
        cp16(s2u(Ks + r * 68 + c), Kg + (long long)((KT) + r) * KVD + c);    \
    }                                                                        \
    CPCOMMIT(); } while (0)
#define V_LOAD2(KT) do {                                                     \
    _Pragma("unroll")                                                        \
    for (int idx = tid * 4; idx < 64 * 64; idx += 1024) {                    \
        int r = idx >> 6, c = idx & 63;                                      \
        cp16(s2u(Vs + r * 72 + c), Vg + (long long)((KT) + r) * KVD + c);    \
    }                                                                        \
    CPCOMMIT(); } while (0)

    K_LOAD2(t0 * 64);   // pending: {K_t0}

    float oacc[2][4][4];
#pragma unroll
    for (int i = 0; i < 2; i++)
#pragma unroll
        for (int j = 0; j < 4; j++)
#pragma unroll
            for (int r = 0; r < 4; r++) oacc[i][j][r] = 0.f;

    for (int t = t0; t < t1; t++) {
        const int kt = t * 64;
        V_LOAD2(kt);            // pending: {K_t, V_t}
        CPWAIT(1);              // K_t done
        __syncthreads();

        float acc[2][4][4];
#pragma unroll
        for (int i = 0; i < 2; i++)
#pragma unroll
            for (int j = 0; j < 4; j++)
#pragma unroll
                for (int r = 0; r < 4; r++) acc[i][j][r] = 0.f;

#pragma unroll
        for (int kk = 0; kk < 64; kk += 8) {
            uint32_t af[2][4], bf[4][2];
#pragma unroll
            for (int i = 0; i < 2; i++) {
                int r = wmS + 16 * i + gid;
                af[i][0] = __float_as_uint(Qs[r * 68 + kk + tig]);
                af[i][1] = __float_as_uint(Qs[(r + 8) * 68 + kk + tig]);
                af[i][2] = __float_as_uint(Qs[r * 68 + kk + tig + 4]);
                af[i][3] = __float_as_uint(Qs[(r + 8) * 68 + kk + tig + 4]);
            }
#pragma unroll
            for (int j = 0; j < 4; j++) {
                int key = wnS + 8 * j + gid;
                bf[j][0] = __float_as_uint(Ks[key * 68 + kk + tig]);
                bf[j][1] = __float_as_uint(Ks[key * 68 + kk + tig + 4]);
            }
#pragma unroll
            for (int i = 0; i < 2; i++)
#pragma unroll
                for (int j = 0; j < 4; j++)
                    mma_tf32(acc[i][j], af[i], bf[j]);
        }
        __syncthreads();        // everyone done reading Ks
        if (t + 1 < t1) K_LOAD2(kt + 64);   // pending: {V_t, K_{t+1}}

        // p = exp2(s) * inv; stage raw fp32 P into Ps
#pragma unroll
        for (int i = 0; i < 2; i++) {
            int r0 = wmS + 16 * i + gid;
            float iv0 = ri[r0], iv1 = ri[r0 + 8];
#pragma unroll
            for (int j = 0; j < 4; j++) {
                int c0 = wnS + 8 * j + 2 * tig;
                float2 w0, w1;
                w0.x = ex2f(acc[i][j][0]) * iv0;
                w0.y = ex2f(acc[i][j][1]) * iv0;
                w1.x = ex2f(acc[i][j][2]) * iv1;
                w1.y = ex2f(acc[i][j][3]) * iv1;
                *reinterpret_cast<float2*>(Ps + r0 * 68 + c0)       = w0;
                *reinterpret_cast<float2*>(Ps + (r0 + 8) * 68 + c0) = w1;
            }
        }
        if (t + 1 < t1) { CPWAIT(1); }   // V_t done (K_{t+1} still flying)
        else            { CPWAIT(0); }   // last tile of this half
        __syncthreads();                 // Ps staged + Vs visible

        // attn write: coalesced float4 rows straight from Ps
#pragma unroll
        for (int idx = tid * 4; idx < 128 * 64; idx += 1024) {
            int r = idx >> 6, c = idx & 63;
            *reinterpret_cast<float4*>(Ag + (long long)r * SS + kt + c) =
                *reinterpret_cast<const float4*>(Ps + r * 68 + c);
        }

        // O += P @ V  (k = 64); P bits fed raw (HW tf32 truncation)
#pragma unroll
        for (int kk = 0; kk < 64; kk += 8) {
            uint32_t af[2][4], bf[4][2];
#pragma unroll
            for (int i = 0; i < 2; i++) {
                int r = wmS + 16 * i + gid;
                af[i][0] = __float_as_uint(Ps[r * 68 + kk + tig]);
                af[i][1] = __float_as_uint(Ps[(r + 8) * 68 + kk + tig]);
                af[i][2] = __float_as_uint(Ps[r * 68 + kk + tig + 4]);
                af[i][3] = __float_as_uint(Ps[(r + 8) * 68 + kk + tig + 4]);
            }
#pragma unroll
            for (int j = 0; j < 4; j++) {
                int c = wnS + 8 * j + gid;
                bf[j][0] = __float_as_uint(Vs[(kk + tig) * 72 + c]);
                bf[j][1] = __float_as_uint(Vs[(kk + tig + 4) * 72 + c]);
            }
#pragma unroll
            for (int i = 0; i < 2; i++)
#pragma unroll
                for (int j = 0; j < 4; j++)
                    mma_tf32(oacc[i][j], af[i], bf[j]);
        }
        __syncthreads();             // Ps / Vs free for next iteration
    }
#undef K_LOAD2
#undef V_LOAD2

    // partial-O epilogue (raw fp32): (B,S,32,64)
    float* Cg = octx + (long long)b * SS * EE + (long long)rb * 128 * EE + h * DD;
#pragma unroll
    for (int i = 0; i < 2; i++) {
        int r0 = wmS + 16 * i + gid;
#pragma unroll
        for (int j = 0; j < 4; j++) {
            int c0 = wnS + 8 * j + 2 * tig;
            float2 o0, o1;
            o0.x = oacc[i][j][0]; o0.y = oacc[i][j][1];
            o1.x = oacc[i][j][2]; o1.y = oacc[i][j][3];
            *reinterpret_cast<float2*>(Cg + (long long)r0 * EE + c0)       = o0;
            *reinterpret_cast<float2*>(Cg + (long long)(r0 + 8) * EE + c0) = o1;
        }
    }
}

// ctx = tf32_round(oct0 + oct1)
__global__ void __launch_bounds__(256)
ctx_combine_kernel(const float* __restrict__ a, const float* __restrict__ b,
                   float* __restrict__ ctx, int n4)
{
    int i = blockIdx.x * 256 + threadIdx.x;
    if (i < n4) {
        float4 x = reinterpret_cast<const float4*>(a)[i];
        float4 y = reinterpret_cast<const float4*>(b)[i];
        float4 o;
        o.x = tfb(x.x + y.x); o.y = tfb(x.y + y.y);
        o.z = tfb(x.z + y.z); o.w = tfb(x.w + y.w);
        reinterpret_cast<float4*>(ctx)[i] = o;
    }
}

// ---------------------------------------------------------------------------
// Launch: out (B,S,E) fp32 first, then attn_weights (B,32,S,S) fp32.
// ---------------------------------------------------------------------------
extern "C" void kernel_launch(void* const* d_in, const int* in_sizes, int n_in,
                              void* d_out, int out_size)
{
    const float* query = (const float*)d_in[0];
    const float* key_  = (const float*)d_in[1];
    const float* value = (const float*)d_in[2];
    const float* Wq = (const float*)d_in[3];  const float* bq = (const float*)d_in[4];
    const float* Wk = (const float*)d_in[5];  const float* bk = (const float*)d_in[6];
    const float* Wv = (const float*)d_in[7];  const float* bv = (const float*)d_in[8];
    const float* Wo = (const float*)d_in[9];  const float* bo = (const float*)d_in[10];

    float* out  = (float*)d_out;
    float* attn = out + (long long)BB * SS * EE;

    float *qbuf, *kbuf, *vbuf, *ctx, *oct0, *oct1, *ps0, *ps1, *rowi;
    float *rqi, *rki, *rvi, *wq, *wk, *wv, *wo;
    cudaGetSymbolAddress((void**)&qbuf, g_q);
    cudaGetSymbolAddress((void**)&kbuf, g_k);
    cudaGetSymbolAddress((void**)&vbuf, g_v);
    cudaGetSymbolAddress((void**)&ctx,  g_ctx);
    cudaGetSymbolAddress((void**)&oct0, g_oct0);
    cudaGetSymbolAddress((void**)&oct1, g_oct1);
    cudaGetSymbolAddress((void**)&ps0,  g_ps0);
    cudaGetSymbolAddress((void**)&ps1,  g_ps1);
    cudaGetSymbolAddress((void**)&rowi, g_rowi);
    cudaGetSymbolAddress((void**)&rqi,  g_rq_in);
    cudaGetSymbolAddress((void**)&rki,  g_rk_in);
    cudaGetSymbolAddress((void**)&rvi,  g_rv_in);
    cudaGetSymbolAddress((void**)&wq,   g_wq);
    cudaGetSymbolAddress((void**)&wk,   g_wk);
    cudaGetSymbolAddress((void**)&wv,   g_wv);
    cudaGetSymbolAddress((void**)&wo,   g_wo);

    static bool attr_set = false;
    if (!attr_set) {
        cudaFuncSetAttribute(qkv_proj_kernel,
            cudaFuncAttributeMaxDynamicSharedMemorySize, PR_BYTES);
        cudaFuncSetAttribute(oproj_kernel,
            cudaFuncAttributeMaxDynamicSharedMemorySize, PR_BYTES);
        cudaFuncSetAttribute(stats_kernel,
            cudaFuncAttributeMaxDynamicSharedMemorySize, ST_BYTES);
        cudaFuncSetAttribute(attnpv_kernel,
            cudaFuncAttributeMaxDynamicSharedMemorySize, P2_BYTES);
        attr_set = true;
    }

    const int M = BB * SS;   // 4096
    dim3 blk(256);

    // Pre-round inputs + weights to tf32 (RNA) — one merged launch.
    round_all_kernel<<<4096, blk>>>(query, key_, value, Wq, Wk, Wv, Wo,
                                    rqi, rki, rvi, wq, wk, wv, wo);

    // Merged Q/K/V projections: 768 tiles, one launch, full machine.
    qkv_proj_kernel<<<768, blk, PR_BYTES>>>(rqi, rki, rvi, wq, wk, wv,
                                            bq, bk, bv, qbuf, kbuf, vbuf);

    // Pass 1: split-K partial row sums of exp2, then combine to 1/sum.
    stats_kernel<<<dim3(SS/128, BB*HQ, 2), blk, ST_BYTES>>>(qbuf, kbuf, ps0, ps1);
    inv_kernel<<<(BB*HQ*SS)/256, blk>>>(ps0, ps1, rowi, BB*HQ*SS);

    // Pass 2: split-K recompute + normalize + attn write + partial P@V.
    attnpv_kernel<<<dim3(SS/128, BB*HQ, 2), blk, P2_BYTES>>>(
        qbuf, kbuf, vbuf, rowi, attn, oct0, oct1);

    // Combine partial O halves (tf32-rounded for cvt-free output proj).
    ctx_combine_kernel<<<(BB*SS*EE/4 + 255)/256, blk>>>(oct0, oct1, ctx, BB*SS*EE/4);

    // Output projection (fp32 out, no out-rounding).
    oproj_kernel<<<dim3(EE/128, M/128), blk, PR_BYTES>>>(ctx, wo, bo, out);
}